// round 15
// baseline (speedup 1.0000x reference)
#include <cuda_runtime.h>
#include <cuda_fp16.h>

#define NN 100000
#define EE 1250000
#define HH 64
#define BN_EPS 1e-5f
#define SCAN_BLOCKS 25   // ceil(NN / 4096); 1024 thr x 4 items
#define ASF_STRIDE 136   // halves; word-stride 68 = 4 mod 32 -> LDSM conflict-free
#define AS_STRIDE  72    // halves; word-stride 36 = 4 mod 32 -> LDSM conflict-free

// ---------------- scratch (static device arrays; no allocation) ----------------
__device__ float g_h0[NN * HH];
__device__ uint2 g_hw16[NN * 16];    // conv0 output (fp16, x dis)
__device__ uint2 g_hw16b[NN * 16];   // fused agg0+conv1 output (fp16, x dis)
__device__ float g_dis[NN];
__device__ int   g_cnt[NN];
__device__ int   g_off[NN + 1];
__device__ int   g_cur[NN];
__device__ int   g_csr[EE];
__device__ int   g_blkflag[128];
__device__ int   g_blkagg[128];
__device__ int   g_blkpref[128];
__device__ __align__(16) __half g_wtfc[64 * ASF_STRIDE];      // fc W^T fp16 [n][k]
__device__ __align__(16) __half g_wtcv[2][64 * AS_STRIDE];    // conv W^T fp16 [n][k]

// ---------------- weight precompute ----------------
__global__ void wconv_k(const float* __restrict__ fcw, const float* __restrict__ cw) {
    int tid = threadIdx.x;
    for (int idx = tid; idx < 64 * 128; idx += 256) {
        int n = idx >> 7, k = idx & 127;
        g_wtfc[n * ASF_STRIDE + k] = __float2half_rn(fcw[k * 64 + n]);
    }
    #pragma unroll
    for (int l = 0; l < 2; l++)
        for (int idx = tid; idx < 64 * 64; idx += 256) {
            int n = idx >> 6, k = idx & 63;
            g_wtcv[l][n * AS_STRIDE + k] = __float2half_rn(cw[l * 4096 + k * 64 + n]);
        }
}

// ---------------- CSR build ----------------
__global__ void zero_k() {
    int i = blockIdx.x * blockDim.x + threadIdx.x;
    if (i * 4 < NN) ((int4*)g_cnt)[i] = make_int4(0, 0, 0, 0);
    if (i < 128) g_blkflag[i] = 0;
}

__global__ void hist_k(const int* __restrict__ dst) {
    int i = blockIdx.x * blockDim.x + threadIdx.x;
    if (i * 4 < EE) {
        int4 d = ((const int4*)dst)[i];
        atomicAdd(&g_cnt[d.x], 1);
        atomicAdd(&g_cnt[d.y], 1);
        atomicAdd(&g_cnt[d.z], 1);
        atomicAdd(&g_cnt[d.w], 1);
    }
}

// shuffle-based scan, 4 items/thread, 3 barriers, decoupled lookback
__global__ __launch_bounds__(1024)
void scanfuse_k() {
    __shared__ int warpsum[32];
    __shared__ int s_total;
    __shared__ int s_pref;
    int b = blockIdx.x, tid = threadIdx.x;
    int lane = tid & 31, w = tid >> 5;
    int idx4 = b * 1024 + tid;
    int base = idx4 * 4;

    int4 v = make_int4(0, 0, 0, 0);
    if (base < NN) v = ((const int4*)g_cnt)[idx4];
    int tsum = v.x + v.y + v.z + v.w;

    int inc = tsum;
    #pragma unroll
    for (int d = 1; d < 32; d <<= 1) {
        int t = __shfl_up_sync(0xFFFFFFFFu, inc, d);
        if (lane >= d) inc += t;
    }
    if (lane == 31) warpsum[w] = inc;
    __syncthreads();

    if (w == 0) {
        int ws = warpsum[lane];
        int winc = ws;
        #pragma unroll
        for (int d = 1; d < 32; d <<= 1) {
            int t = __shfl_up_sync(0xFFFFFFFFu, winc, d);
            if (lane >= d) winc += t;
        }
        warpsum[lane] = winc - ws;
        if (lane == 31) s_total = winc;
    }
    __syncthreads();

    if (tid == 0) {
        int total = s_total;
        g_blkagg[b] = total;
        __threadfence();
        atomicExch(&g_blkflag[b], 1);
        int pref = 0;
        for (int p = b - 1; p >= 0; ) {
            int f = atomicAdd(&g_blkflag[p], 0);
            if (f == 2)      { pref += atomicAdd(&g_blkpref[p], 0); break; }
            else if (f == 1) { pref += atomicAdd(&g_blkagg[p], 0);  p--;   }
        }
        g_blkpref[b] = pref + total;
        __threadfence();
        atomicExch(&g_blkflag[b], 2);
        s_pref = pref;
    }
    __syncthreads();

    if (base < NN) {
        int off0 = s_pref + warpsum[w] + (inc - tsum);
        int off1 = off0 + v.x;
        int off2 = off1 + v.y;
        int off3 = off2 + v.z;
        ((int4*)g_off)[idx4] = make_int4(off0, off1, off2, off3);
        ((int4*)g_cur)[idx4] = make_int4(off0, off1, off2, off3);
        float4 d4;
        d4.x = rsqrtf((float)(v.x + 1));
        d4.y = rsqrtf((float)(v.y + 1));
        d4.z = rsqrtf((float)(v.z + 1));
        d4.w = rsqrtf((float)(v.w + 1));
        ((float4*)g_dis)[idx4] = d4;
    }
    if (b == 0 && tid == 0) g_off[NN] = EE;
}

__global__ void fill_k(const int* __restrict__ src, const int* __restrict__ dst) {
    int i = blockIdx.x * blockDim.x + threadIdx.x;
    if (i * 4 < EE) {
        int4 d = ((const int4*)dst)[i];
        int4 s = ((const int4*)src)[i];
        g_csr[atomicAdd(&g_cur[d.x], 1)] = s.x;
        g_csr[atomicAdd(&g_cur[d.y], 1)] = s.y;
        g_csr[atomicAdd(&g_cur[d.z], 1)] = s.z;
        g_csr[atomicAdd(&g_cur[d.w], 1)] = s.w;
    }
}

// ---------------- ldmatrix helper ----------------
__device__ __forceinline__ void ldsm4(unsigned& r0, unsigned& r1, unsigned& r2, unsigned& r3,
                                      const __half* p) {
    unsigned a = (unsigned)__cvta_generic_to_shared(p);
    asm volatile("ldmatrix.sync.aligned.m8n8.x4.shared.b16 {%0,%1,%2,%3}, [%4];"
                 : "=r"(r0), "=r"(r1), "=r"(r2), "=r"(r3) : "r"(a));
}

// ---------------- fc GEMM via HMMA + LDSM (K=128) ----------------
__global__ __launch_bounds__(256)
void gemmh_fc_k(const float* __restrict__ A,
                float* __restrict__ out,
                const float* __restrict__ fcb, const float* __restrict__ bng,
                const float* __restrict__ bnb, const float* __restrict__ bnm,
                const float* __restrict__ bnv)
{
    __shared__ __align__(16) __half As[64 * ASF_STRIDE];
    __shared__ __align__(16) __half Ws[64 * ASF_STRIDE];

    int tid = threadIdx.x;
    int row0 = blockIdx.x * 64;
    int wid = tid >> 5, lane = tid & 31;
    int g = lane >> 2, t = lane & 3;
    int lr = lane & 7, quad = lane >> 3;
    int warpM = (wid & 1) * 32;
    int warpN = (wid >> 1) * 16;

    #pragma unroll
    for (int i = 0; i < 8; i++) {
        int idx = tid + i * 256;
        int r = idx >> 5, c4 = idx & 31;
        int grow = row0 + r;
        float4 v = make_float4(0.f, 0.f, 0.f, 0.f);
        if (grow < NN)
            v = *(const float4*)&A[(long)grow * 128 + c4 * 4];
        __half2 h01 = __floats2half2_rn(v.x, v.y);
        __half2 h23 = __floats2half2_rn(v.z, v.w);
        uint2 u;
        u.x = *(unsigned*)&h01;
        u.y = *(unsigned*)&h23;
        *(uint2*)&As[r * ASF_STRIDE + c4 * 4] = u;
    }
    {
        const uint4* srcW = (const uint4*)g_wtfc;
        uint4* dstW = (uint4*)Ws;
        #pragma unroll
        for (int i = 0; i < 5; i++) {
            int idx = tid + i * 256;
            if (idx < 64 * ASF_STRIDE / 8) dstW[idx] = srcW[idx];
        }
    }
    __syncthreads();

    float c[2][2][4];
    #pragma unroll
    for (int m = 0; m < 2; m++)
        #pragma unroll
        for (int n = 0; n < 2; n++)
            #pragma unroll
            for (int q = 0; q < 4; q++) c[m][n][q] = 0.f;

    int bn = warpN + lr + ((quad & 2) ? 8 : 0);
    int bko = (quad & 1) ? 8 : 0;
    int arl = lr + ((quad & 1) ? 8 : 0);
    int ako = (quad & 2) ? 8 : 0;

    #pragma unroll
    for (int kc = 0; kc < 128; kc += 16) {
        unsigned b0, b1, b2, b3;
        ldsm4(b0, b1, b2, b3, &Ws[bn * ASF_STRIDE + kc + bko]);
        #pragma unroll
        for (int mf = 0; mf < 2; mf++) {
            unsigned a0, a1, a2, a3;
            ldsm4(a0, a1, a2, a3, &As[(warpM + mf * 16 + arl) * ASF_STRIDE + kc + ako]);
            asm volatile(
                "mma.sync.aligned.m16n8k16.row.col.f32.f16.f16.f32 "
                "{%0,%1,%2,%3}, {%4,%5,%6,%7}, {%8,%9}, {%0,%1,%2,%3};"
                : "+f"(c[mf][0][0]), "+f"(c[mf][0][1]), "+f"(c[mf][0][2]), "+f"(c[mf][0][3])
                : "r"(a0), "r"(a1), "r"(a2), "r"(a3), "r"(b0), "r"(b1));
            asm volatile(
                "mma.sync.aligned.m16n8k16.row.col.f32.f16.f16.f32 "
                "{%0,%1,%2,%3}, {%4,%5,%6,%7}, {%8,%9}, {%0,%1,%2,%3};"
                : "+f"(c[mf][1][0]), "+f"(c[mf][1][1]), "+f"(c[mf][1][2]), "+f"(c[mf][1][3])
                : "r"(a0), "r"(a1), "r"(a2), "r"(a3), "r"(b2), "r"(b3));
        }
    }

    #pragma unroll
    for (int nf = 0; nf < 2; nf++) {
        int col = warpN + nf * 8 + 2 * t;
        float sc0 = bng[col]     * rsqrtf(bnv[col]     + BN_EPS);
        float sc1 = bng[col + 1] * rsqrtf(bnv[col + 1] + BN_EPS);
        float m0 = bnm[col], m1 = bnm[col + 1];
        float bb0 = bnb[col], bb1 = bnb[col + 1];
        float f0 = fcb[col], f1 = fcb[col + 1];
        #pragma unroll
        for (int mf = 0; mf < 2; mf++) {
            int r1 = row0 + warpM + mf * 16 + g;
            int r2 = r1 + 8;
            if (r1 < NN) {
                float2 o;
                o.x = fmaxf((c[mf][nf][0] + f0 - m0) * sc0 + bb0, 0.f);
                o.y = fmaxf((c[mf][nf][1] + f1 - m1) * sc1 + bb1, 0.f);
                *(float2*)&out[(long)r1 * HH + col] = o;
            }
            if (r2 < NN) {
                float2 o;
                o.x = fmaxf((c[mf][nf][2] + f0 - m0) * sc0 + bb0, 0.f);
                o.y = fmaxf((c[mf][nf][3] + f1 - m1) * sc1 + bb1, 0.f);
                *(float2*)&out[(long)r2 * HH + col] = o;
            }
        }
    }
}

// ---------------- conv0 GEMM via HMMA + LDSM (K=64) ----------------
__global__ __launch_bounds__(256)
void gemmh_k(const float* __restrict__ A, const __half* __restrict__ Wt,
             uint2* __restrict__ out)
{
    __shared__ __align__(16) __half As[64 * AS_STRIDE];
    __shared__ __align__(16) __half Ws[64 * AS_STRIDE];

    int tid = threadIdx.x;
    int row0 = blockIdx.x * 64;
    int wid = tid >> 5, lane = tid & 31;
    int g = lane >> 2, t = lane & 3;
    int lr = lane & 7, quad = lane >> 3;
    int warpM = (wid & 1) * 32;
    int warpN = (wid >> 1) * 16;

    #pragma unroll
    for (int i = 0; i < 4; i++) {
        int idx = tid + i * 256;
        int r = idx >> 4, c4 = idx & 15;
        int grow = row0 + r;
        float4 v = make_float4(0.f, 0.f, 0.f, 0.f);
        if (grow < NN)
            v = *(const float4*)&A[(long)grow * HH + c4 * 4];
        __half2 h01 = __floats2half2_rn(v.x, v.y);
        __half2 h23 = __floats2half2_rn(v.z, v.w);
        uint2 u;
        u.x = *(unsigned*)&h01;
        u.y = *(unsigned*)&h23;
        *(uint2*)&As[r * AS_STRIDE + c4 * 4] = u;
    }
    {
        const uint4* srcW = (const uint4*)Wt;
        uint4* dstW = (uint4*)Ws;
        #pragma unroll
        for (int i = 0; i < 3; i++) {
            int idx = tid + i * 256;
            if (idx < 64 * AS_STRIDE / 8) dstW[idx] = srcW[idx];
        }
    }
    __syncthreads();

    float c[2][2][4];
    #pragma unroll
    for (int m = 0; m < 2; m++)
        #pragma unroll
        for (int n = 0; n < 2; n++)
            #pragma unroll
            for (int q = 0; q < 4; q++) c[m][n][q] = 0.f;

    int bn = warpN + lr + ((quad & 2) ? 8 : 0);
    int bko = (quad & 1) ? 8 : 0;
    int arl = lr + ((quad & 1) ? 8 : 0);
    int ako = (quad & 2) ? 8 : 0;

    #pragma unroll
    for (int kc = 0; kc < 64; kc += 16) {
        unsigned b0, b1, b2, b3;
        ldsm4(b0, b1, b2, b3, &Ws[bn * AS_STRIDE + kc + bko]);
        #pragma unroll
        for (int mf = 0; mf < 2; mf++) {
            unsigned a0, a1, a2, a3;
            ldsm4(a0, a1, a2, a3, &As[(warpM + mf * 16 + arl) * AS_STRIDE + kc + ako]);
            asm volatile(
                "mma.sync.aligned.m16n8k16.row.col.f32.f16.f16.f32 "
                "{%0,%1,%2,%3}, {%4,%5,%6,%7}, {%8,%9}, {%0,%1,%2,%3};"
                : "+f"(c[mf][0][0]), "+f"(c[mf][0][1]), "+f"(c[mf][0][2]), "+f"(c[mf][0][3])
                : "r"(a0), "r"(a1), "r"(a2), "r"(a3), "r"(b0), "r"(b1));
            asm volatile(
                "mma.sync.aligned.m16n8k16.row.col.f32.f16.f16.f32 "
                "{%0,%1,%2,%3}, {%4,%5,%6,%7}, {%8,%9}, {%0,%1,%2,%3};"
                : "+f"(c[mf][1][0]), "+f"(c[mf][1][1]), "+f"(c[mf][1][2]), "+f"(c[mf][1][3])
                : "r"(a0), "r"(a1), "r"(a2), "r"(a3), "r"(b2), "r"(b3));
        }
    }

    __half* hw = (__half*)out;
    #pragma unroll
    for (int mf = 0; mf < 2; mf++) {
        int r1 = row0 + warpM + mf * 16 + g;
        int r2 = r1 + 8;
        float d1 = (r1 < NN) ? g_dis[r1] : 0.f;
        float d2 = (r2 < NN) ? g_dis[r2] : 0.f;
        #pragma unroll
        for (int nf = 0; nf < 2; nf++) {
            int col = warpN + nf * 8 + 2 * t;
            if (r1 < NN) {
                __half2 h = __floats2half2_rn(c[mf][nf][0] * d1, c[mf][nf][1] * d1);
                *(__half2*)&hw[(long)r1 * HH + col] = h;
            }
            if (r2 < NN) {
                __half2 h = __floats2half2_rn(c[mf][nf][2] * d2, c[mf][nf][3] * d2);
                *(__half2*)&hw[(long)r2 * HH + col] = h;
            }
        }
    }
}

// ---------------- FUSED: agg0 (+bn1+relu+residual) -> conv1 HMMA -> x dis ----------------
// 1024 threads, 64 nodes/block. Gather: 16 thr/node into fp16 smem tile.
// MMA: 32 warps, warp tile m16n8 (4x8 tiling of 64x64), K=64.
__global__ __launch_bounds__(1024)
void aggconv_k(const uint2* __restrict__ hwu, const __half* __restrict__ Wt,
               const float* __restrict__ cb, const float* __restrict__ bng,
               const float* __restrict__ bnb, const float* __restrict__ bnm,
               const float* __restrict__ bnv, const float* __restrict__ last,
               uint2* __restrict__ out)
{
    __shared__ __align__(16) __half As[64 * AS_STRIDE];
    __shared__ __align__(16) __half Ws[64 * AS_STRIDE];

    int tid = threadIdx.x;
    int node0 = blockIdx.x * 64;

    // Ws load: 64*72/8 = 576 uint4
    if (tid < 576) ((uint4*)Ws)[tid] = ((const uint4*)Wt)[tid];

    // ---- gather phase (identical float ops to agg_k) ----
    int nl = tid >> 4, c4 = tid & 15;
    int node = node0 + nl;
    if (node < NN) {
        uint2 rs = hwu[node * 16 + c4];
        float2 f01 = __half22float2(*(const __half2*)&rs.x);
        float2 f23 = __half22float2(*(const __half2*)&rs.y);
        float4 acc = make_float4(f01.x, f01.y, f23.x, f23.y);
        float4 accB = make_float4(0.f, 0.f, 0.f, 0.f);

        int s = g_off[node], e = g_off[node + 1];
        int i = s;
        for (; i + 1 < e; i += 2) {
            int u0 = g_csr[i];
            int u1 = g_csr[i + 1];
            uint2 r0 = hwu[u0 * 16 + c4];
            uint2 r1 = hwu[u1 * 16 + c4];
            float2 a01 = __half22float2(*(const __half2*)&r0.x);
            float2 a23 = __half22float2(*(const __half2*)&r0.y);
            float2 b01 = __half22float2(*(const __half2*)&r1.x);
            float2 b23 = __half22float2(*(const __half2*)&r1.y);
            acc.x += a01.x; acc.y += a01.y; acc.z += a23.x; acc.w += a23.y;
            accB.x += b01.x; accB.y += b01.y; accB.z += b23.x; accB.w += b23.y;
        }
        if (i < e) {
            int u = g_csr[i];
            uint2 r0 = hwu[u * 16 + c4];
            float2 a01 = __half22float2(*(const __half2*)&r0.x);
            float2 a23 = __half22float2(*(const __half2*)&r0.y);
            acc.x += a01.x; acc.y += a01.y; acc.z += a23.x; acc.w += a23.y;
        }
        acc.x += accB.x; acc.y += accB.y; acc.z += accB.z; acc.w += accB.w;

        float dn = g_dis[node];
        int c = c4 * 4;
        float4 B  = *(const float4*)&cb[c];
        float4 G  = *(const float4*)&bng[c];
        float4 Be = *(const float4*)&bnb[c];
        float4 M  = *(const float4*)&bnm[c];
        float4 V  = *(const float4*)&bnv[c];
        float4 Ls = ((const float4*)last)[node * 16 + c4];

        float4 h;
        h.x = fmaxf((acc.x * dn + B.x - M.x) * (G.x * rsqrtf(V.x + BN_EPS)) + Be.x, 0.f) + Ls.x;
        h.y = fmaxf((acc.y * dn + B.y - M.y) * (G.y * rsqrtf(V.y + BN_EPS)) + Be.y, 0.f) + Ls.y;
        h.z = fmaxf((acc.z * dn + B.z - M.z) * (G.z * rsqrtf(V.z + BN_EPS)) + Be.z, 0.f) + Ls.z;
        h.w = fmaxf((acc.w * dn + B.w - M.w) * (G.w * rsqrtf(V.w + BN_EPS)) + Be.w, 0.f) + Ls.w;

        __half2 h01 = __floats2half2_rn(h.x, h.y);
        __half2 h23 = __floats2half2_rn(h.z, h.w);
        uint2 u;
        u.x = *(unsigned*)&h01;
        u.y = *(unsigned*)&h23;
        *(uint2*)&As[nl * AS_STRIDE + c] = u;
    }
    __syncthreads();

    // ---- HMMA phase: 32 warps, each m16n8, K=64 ----
    int wid = tid >> 5, lane = tid & 31;
    int g = lane >> 2, t = lane & 3;
    int warpM = (wid & 3) * 16;
    int warpN = (wid >> 2) * 8;

    float c0 = 0.f, c1 = 0.f, c2 = 0.f, c3 = 0.f;

    // A ldsm address (m16k16): row = warpM + (lane&15), kofs = (lane>>4)*8
    const __half* aAddrBase = &As[(warpM + (lane & 15)) * AS_STRIDE + ((lane >> 4) ? 8 : 0)];
    // B ldsm address (n8 x k32 via x4): row = warpN + (lane&7), kofs = (lane>>3)*8
    const __half* bAddrBase = &Ws[(warpN + (lane & 7)) * AS_STRIDE + (lane >> 3) * 8];

    #pragma unroll
    for (int kb = 0; kb < 64; kb += 32) {
        unsigned b0, b1, b2, b3;
        ldsm4(b0, b1, b2, b3, bAddrBase + kb);
        #pragma unroll
        for (int kk = 0; kk < 2; kk++) {
            int kc = kb + kk * 16;
            unsigned a0, a1, a2, a3;
            ldsm4(a0, a1, a2, a3, aAddrBase + kc);
            unsigned bb0 = kk == 0 ? b0 : b2;
            unsigned bb1 = kk == 0 ? b1 : b3;
            asm volatile(
                "mma.sync.aligned.m16n8k16.row.col.f32.f16.f16.f32 "
                "{%0,%1,%2,%3}, {%4,%5,%6,%7}, {%8,%9}, {%0,%1,%2,%3};"
                : "+f"(c0), "+f"(c1), "+f"(c2), "+f"(c3)
                : "r"(a0), "r"(a1), "r"(a2), "r"(a3), "r"(bb0), "r"(bb1));
        }
    }

    // epilogue: x dis, fp16 out
    __half* hw = (__half*)out;
    int r1 = node0 + warpM + g;
    int r2 = r1 + 8;
    int col = warpN + 2 * t;
    if (r1 < NN) {
        float d1 = g_dis[r1];
        __half2 h = __floats2half2_rn(c0 * d1, c1 * d1);
        *(__half2*)&hw[(long)r1 * HH + col] = h;
    }
    if (r2 < NN) {
        float d2 = g_dis[r2];
        __half2 h = __floats2half2_rn(c2 * d2, c3 * d2);
        *(__half2*)&hw[(long)r2 * HH + col] = h;
    }
}

// ---------------- final aggregation: 16 threads/node, uint2 fp16 gathers ----------------
__global__ __launch_bounds__(256)
void agg_k(const uint2* __restrict__ hwu,
           const float* __restrict__ cb, const float* __restrict__ bng,
           const float* __restrict__ bnb, const float* __restrict__ bnm,
           const float* __restrict__ bnv, const float* __restrict__ last,
           float* __restrict__ out)
{
    int gid = blockIdx.x * blockDim.x + threadIdx.x;
    int node = gid >> 4;
    if (node >= NN) return;
    int c4 = gid & 15;

    uint2 rs = hwu[node * 16 + c4];
    float2 f01 = __half22float2(*(const __half2*)&rs.x);
    float2 f23 = __half22float2(*(const __half2*)&rs.y);
    float4 acc = make_float4(f01.x, f01.y, f23.x, f23.y);
    float4 accB = make_float4(0.f, 0.f, 0.f, 0.f);

    int s = g_off[node], e = g_off[node + 1];
    int i = s;
    for (; i + 1 < e; i += 2) {
        int u0 = g_csr[i];
        int u1 = g_csr[i + 1];
        uint2 r0 = hwu[u0 * 16 + c4];
        uint2 r1 = hwu[u1 * 16 + c4];
        float2 a01 = __half22float2(*(const __half2*)&r0.x);
        float2 a23 = __half22float2(*(const __half2*)&r0.y);
        float2 b01 = __half22float2(*(const __half2*)&r1.x);
        float2 b23 = __half22float2(*(const __half2*)&r1.y);
        acc.x += a01.x; acc.y += a01.y; acc.z += a23.x; acc.w += a23.y;
        accB.x += b01.x; accB.y += b01.y; accB.z += b23.x; accB.w += b23.y;
    }
    if (i < e) {
        int u = g_csr[i];
        uint2 r0 = hwu[u * 16 + c4];
        float2 a01 = __half22float2(*(const __half2*)&r0.x);
        float2 a23 = __half22float2(*(const __half2*)&r0.y);
        acc.x += a01.x; acc.y += a01.y; acc.z += a23.x; acc.w += a23.y;
    }
    acc.x += accB.x; acc.y += accB.y; acc.z += accB.z; acc.w += accB.w;

    float dn = g_dis[node];
    int c = c4 * 4;
    float4 B  = *(const float4*)&cb[c];
    float4 G  = *(const float4*)&bng[c];
    float4 Be = *(const float4*)&bnb[c];
    float4 M  = *(const float4*)&bnm[c];
    float4 V  = *(const float4*)&bnv[c];
    float4 Ls = ((const float4*)last)[node * 16 + c4];

    float4 o;
    o.x = fmaxf((acc.x * dn + B.x - M.x) * (G.x * rsqrtf(V.x + BN_EPS)) + Be.x, 0.f) + Ls.x;
    o.y = fmaxf((acc.y * dn + B.y - M.y) * (G.y * rsqrtf(V.y + BN_EPS)) + Be.y, 0.f) + Ls.y;
    o.z = fmaxf((acc.z * dn + B.z - M.z) * (G.z * rsqrtf(V.z + BN_EPS)) + Be.z, 0.f) + Ls.z;
    o.w = fmaxf((acc.w * dn + B.w - M.w) * (G.w * rsqrtf(V.w + BN_EPS)) + Be.w, 0.f) + Ls.w;
    ((float4*)out)[node * 16 + c4] = o;
}

// ---------------- launch ----------------
// Issue order: wconv(1,s1) zero(2) hist(3) fc(4,s1 -> profiled) scanfuse(5)
//              fill(6) conv0(7,s1) ... join ... aggconv, agg1
extern "C" void kernel_launch(void* const* d_in, const int* in_sizes, int n_in,
                              void* d_out, int out_size)
{
    const float* x   = (const float*)d_in[0];
    const int*   ei  = (const int*)  d_in[1];
    const float* fcw = (const float*)d_in[2];
    const float* fcb = (const float*)d_in[3];
    const float* cw  = (const float*)d_in[4];
    const float* cb  = (const float*)d_in[5];
    const float* bng = (const float*)d_in[6];
    const float* bnb = (const float*)d_in[7];
    const float* bnm = (const float*)d_in[8];
    const float* bnv = (const float*)d_in[9];
    float* out = (float*)d_out;

    const int* src = ei;
    const int* dst = ei + EE;

    float* ph0;
    uint2 *phw, *phwb;
    __half *pwt0, *pwt1;
    cudaGetSymbolAddress((void**)&ph0, g_h0);
    cudaGetSymbolAddress((void**)&phw, g_hw16);
    cudaGetSymbolAddress((void**)&phwb, g_hw16b);
    cudaGetSymbolAddress((void**)&pwt0, g_wtcv);
    pwt1 = pwt0 + 64 * AS_STRIDE;

    cudaStream_t s1;
    cudaEvent_t evFork, evScan, evJoin;
    cudaStreamCreateWithFlags(&s1, cudaStreamNonBlocking);
    cudaEventCreateWithFlags(&evFork, cudaEventDisableTiming);
    cudaEventCreateWithFlags(&evScan, cudaEventDisableTiming);
    cudaEventCreateWithFlags(&evJoin, cudaEventDisableTiming);

    const int gblocks = (NN + 63) / 64;
    const int ablocks = (NN * 16 + 255) / 256;

    cudaEventRecord(evFork, 0);
    cudaStreamWaitEvent(s1, evFork, 0);

    // slots 1-3
    wconv_k<<<1, 256, 0, s1>>>(fcw, cw);
    zero_k <<<(NN / 4 + 255) / 256, 256>>>();
    hist_k <<<(EE / 4 + 255) / 256, 256>>>(dst);

    // slot 4 (profiled): LDSM fc GEMM
    gemmh_fc_k<<<gblocks, 256, 0, s1>>>(x, ph0, fcb, bng, bnb, bnm, bnv);

    scanfuse_k<<<SCAN_BLOCKS, 1024>>>();
    cudaEventRecord(evScan, 0);               // g_dis + g_cur ready
    fill_k<<<(EE / 4 + 255) / 256, 256>>>(src, dst);

    // conv0 needs g_dis
    cudaStreamWaitEvent(s1, evScan, 0);
    gemmh_k<<<gblocks, 256, 0, s1>>>(ph0, pwt0, phw);

    cudaEventRecord(evJoin, s1);
    cudaStreamWaitEvent(0, evJoin, 0);

    // fused agg0 + bn1 + relu + residual + conv1 HMMA + dis
    aggconv_k<<<gblocks, 1024>>>(phw, pwt1,
                                 cb, bng + 64, bnb + 64, bnm + 64, bnv + 64,
                                 ph0, phwb);

    // final aggregation -> d_out
    agg_k<<<ablocks, 256>>>(phwb, cb + HH, bng + 128, bnb + 128, bnm + 128, bnv + 128,
                            ph0, out);

    cudaEventDestroy(evFork);
    cudaEventDestroy(evScan);
    cudaEventDestroy(evJoin);
    cudaStreamDestroy(s1);
}

// round 16
// speedup vs baseline: 1.0861x; 1.0861x over previous
#include <cuda_runtime.h>
#include <cuda_fp16.h>

#define NN 100000
#define EE 1250000
#define HH 64
#define BN_EPS 1e-5f
#define SCAN_BLOCKS 25   // ceil(NN / 4096); 1024 thr x 4 items
#define ASF_STRIDE 136   // halves; word-stride 68 = 4 mod 32 -> LDSM conflict-free
#define AS_STRIDE  72    // halves; word-stride 36 = 4 mod 32 -> LDSM conflict-free

// ---------------- scratch (static device arrays; no allocation) ----------------
__device__ float g_h0[NN * HH];      // post-fc activation (residual source)
__device__ uint2 g_hw16[NN * 16];    // conv0 output (fp16, x dis)
__device__ uint2 g_h1h[NN * 16];     // agg0 output as fp16 (input to conv1)
__device__ float g_dis[NN];
__device__ int   g_cnt[NN];
__device__ int   g_off[NN + 1];
__device__ int   g_cur[NN];
__device__ int   g_csr[EE];
__device__ int   g_blkflag[128];
__device__ int   g_blkagg[128];
__device__ int   g_blkpref[128];
__device__ __align__(16) __half g_wtfc[64 * ASF_STRIDE];      // fc W^T fp16 [n][k]
__device__ __align__(16) __half g_wtcv[2][64 * AS_STRIDE];    // conv W^T fp16 [n][k]

// ---------------- weight precompute ----------------
__global__ void wconv_k(const float* __restrict__ fcw, const float* __restrict__ cw) {
    int tid = threadIdx.x;
    for (int idx = tid; idx < 64 * 128; idx += 256) {
        int n = idx >> 7, k = idx & 127;
        g_wtfc[n * ASF_STRIDE + k] = __float2half_rn(fcw[k * 64 + n]);
    }
    #pragma unroll
    for (int l = 0; l < 2; l++)
        for (int idx = tid; idx < 64 * 64; idx += 256) {
            int n = idx >> 6, k = idx & 63;
            g_wtcv[l][n * AS_STRIDE + k] = __float2half_rn(cw[l * 4096 + k * 64 + n]);
        }
}

// ---------------- CSR build ----------------
__global__ void zero_k() {
    int i = blockIdx.x * blockDim.x + threadIdx.x;
    if (i * 4 < NN) ((int4*)g_cnt)[i] = make_int4(0, 0, 0, 0);
    if (i < 128) g_blkflag[i] = 0;
}

__global__ void hist_k(const int* __restrict__ dst) {
    int i = blockIdx.x * blockDim.x + threadIdx.x;
    if (i * 4 < EE) {
        int4 d = ((const int4*)dst)[i];
        atomicAdd(&g_cnt[d.x], 1);
        atomicAdd(&g_cnt[d.y], 1);
        atomicAdd(&g_cnt[d.z], 1);
        atomicAdd(&g_cnt[d.w], 1);
    }
}

// shuffle-based scan, 4 items/thread, 3 barriers, decoupled lookback
__global__ __launch_bounds__(1024)
void scanfuse_k() {
    __shared__ int warpsum[32];
    __shared__ int s_total;
    __shared__ int s_pref;
    int b = blockIdx.x, tid = threadIdx.x;
    int lane = tid & 31, w = tid >> 5;
    int idx4 = b * 1024 + tid;
    int base = idx4 * 4;

    int4 v = make_int4(0, 0, 0, 0);
    if (base < NN) v = ((const int4*)g_cnt)[idx4];
    int tsum = v.x + v.y + v.z + v.w;

    int inc = tsum;
    #pragma unroll
    for (int d = 1; d < 32; d <<= 1) {
        int t = __shfl_up_sync(0xFFFFFFFFu, inc, d);
        if (lane >= d) inc += t;
    }
    if (lane == 31) warpsum[w] = inc;
    __syncthreads();

    if (w == 0) {
        int ws = warpsum[lane];
        int winc = ws;
        #pragma unroll
        for (int d = 1; d < 32; d <<= 1) {
            int t = __shfl_up_sync(0xFFFFFFFFu, winc, d);
            if (lane >= d) winc += t;
        }
        warpsum[lane] = winc - ws;
        if (lane == 31) s_total = winc;
    }
    __syncthreads();

    if (tid == 0) {
        int total = s_total;
        g_blkagg[b] = total;
        __threadfence();
        atomicExch(&g_blkflag[b], 1);
        int pref = 0;
        for (int p = b - 1; p >= 0; ) {
            int f = atomicAdd(&g_blkflag[p], 0);
            if (f == 2)      { pref += atomicAdd(&g_blkpref[p], 0); break; }
            else if (f == 1) { pref += atomicAdd(&g_blkagg[p], 0);  p--;   }
        }
        g_blkpref[b] = pref + total;
        __threadfence();
        atomicExch(&g_blkflag[b], 2);
        s_pref = pref;
    }
    __syncthreads();

    if (base < NN) {
        int off0 = s_pref + warpsum[w] + (inc - tsum);
        int off1 = off0 + v.x;
        int off2 = off1 + v.y;
        int off3 = off2 + v.z;
        ((int4*)g_off)[idx4] = make_int4(off0, off1, off2, off3);
        ((int4*)g_cur)[idx4] = make_int4(off0, off1, off2, off3);
        float4 d4;
        d4.x = rsqrtf((float)(v.x + 1));
        d4.y = rsqrtf((float)(v.y + 1));
        d4.z = rsqrtf((float)(v.z + 1));
        d4.w = rsqrtf((float)(v.w + 1));
        ((float4*)g_dis)[idx4] = d4;
    }
    if (b == 0 && tid == 0) g_off[NN] = EE;
}

__global__ void fill_k(const int* __restrict__ src, const int* __restrict__ dst) {
    int i = blockIdx.x * blockDim.x + threadIdx.x;
    if (i * 4 < EE) {
        int4 d = ((const int4*)dst)[i];
        int4 s = ((const int4*)src)[i];
        g_csr[atomicAdd(&g_cur[d.x], 1)] = s.x;
        g_csr[atomicAdd(&g_cur[d.y], 1)] = s.y;
        g_csr[atomicAdd(&g_cur[d.z], 1)] = s.z;
        g_csr[atomicAdd(&g_cur[d.w], 1)] = s.w;
    }
}

// ---------------- ldmatrix helper ----------------
__device__ __forceinline__ void ldsm4(unsigned& r0, unsigned& r1, unsigned& r2, unsigned& r3,
                                      const __half* p) {
    unsigned a = (unsigned)__cvta_generic_to_shared(p);
    asm volatile("ldmatrix.sync.aligned.m8n8.x4.shared.b16 {%0,%1,%2,%3}, [%4];"
                 : "=r"(r0), "=r"(r1), "=r"(r2), "=r"(r3) : "r"(a));
}

// ---------------- fc GEMM via HMMA + LDSM (K=128) ----------------
__global__ __launch_bounds__(256)
void gemmh_fc_k(const float* __restrict__ A,
                float* __restrict__ out,
                const float* __restrict__ fcb, const float* __restrict__ bng,
                const float* __restrict__ bnb, const float* __restrict__ bnm,
                const float* __restrict__ bnv)
{
    __shared__ __align__(16) __half As[64 * ASF_STRIDE];
    __shared__ __align__(16) __half Ws[64 * ASF_STRIDE];

    int tid = threadIdx.x;
    int row0 = blockIdx.x * 64;
    int wid = tid >> 5, lane = tid & 31;
    int g = lane >> 2, t = lane & 3;
    int lr = lane & 7, quad = lane >> 3;
    int warpM = (wid & 1) * 32;
    int warpN = (wid >> 1) * 16;

    #pragma unroll
    for (int i = 0; i < 8; i++) {
        int idx = tid + i * 256;
        int r = idx >> 5, c4 = idx & 31;
        int grow = row0 + r;
        float4 v = make_float4(0.f, 0.f, 0.f, 0.f);
        if (grow < NN)
            v = *(const float4*)&A[(long)grow * 128 + c4 * 4];
        __half2 h01 = __floats2half2_rn(v.x, v.y);
        __half2 h23 = __floats2half2_rn(v.z, v.w);
        uint2 u;
        u.x = *(unsigned*)&h01;
        u.y = *(unsigned*)&h23;
        *(uint2*)&As[r * ASF_STRIDE + c4 * 4] = u;
    }
    {
        const uint4* srcW = (const uint4*)g_wtfc;
        uint4* dstW = (uint4*)Ws;
        #pragma unroll
        for (int i = 0; i < 5; i++) {
            int idx = tid + i * 256;
            if (idx < 64 * ASF_STRIDE / 8) dstW[idx] = srcW[idx];
        }
    }
    __syncthreads();

    float c[2][2][4];
    #pragma unroll
    for (int m = 0; m < 2; m++)
        #pragma unroll
        for (int n = 0; n < 2; n++)
            #pragma unroll
            for (int q = 0; q < 4; q++) c[m][n][q] = 0.f;

    int bn = warpN + lr + ((quad & 2) ? 8 : 0);
    int bko = (quad & 1) ? 8 : 0;
    int arl = lr + ((quad & 1) ? 8 : 0);
    int ako = (quad & 2) ? 8 : 0;

    #pragma unroll
    for (int kc = 0; kc < 128; kc += 16) {
        unsigned b0, b1, b2, b3;
        ldsm4(b0, b1, b2, b3, &Ws[bn * ASF_STRIDE + kc + bko]);
        #pragma unroll
        for (int mf = 0; mf < 2; mf++) {
            unsigned a0, a1, a2, a3;
            ldsm4(a0, a1, a2, a3, &As[(warpM + mf * 16 + arl) * ASF_STRIDE + kc + ako]);
            asm volatile(
                "mma.sync.aligned.m16n8k16.row.col.f32.f16.f16.f32 "
                "{%0,%1,%2,%3}, {%4,%5,%6,%7}, {%8,%9}, {%0,%1,%2,%3};"
                : "+f"(c[mf][0][0]), "+f"(c[mf][0][1]), "+f"(c[mf][0][2]), "+f"(c[mf][0][3])
                : "r"(a0), "r"(a1), "r"(a2), "r"(a3), "r"(b0), "r"(b1));
            asm volatile(
                "mma.sync.aligned.m16n8k16.row.col.f32.f16.f16.f32 "
                "{%0,%1,%2,%3}, {%4,%5,%6,%7}, {%8,%9}, {%0,%1,%2,%3};"
                : "+f"(c[mf][1][0]), "+f"(c[mf][1][1]), "+f"(c[mf][1][2]), "+f"(c[mf][1][3])
                : "r"(a0), "r"(a1), "r"(a2), "r"(a3), "r"(b2), "r"(b3));
        }
    }

    #pragma unroll
    for (int nf = 0; nf < 2; nf++) {
        int col = warpN + nf * 8 + 2 * t;
        float sc0 = bng[col]     * rsqrtf(bnv[col]     + BN_EPS);
        float sc1 = bng[col + 1] * rsqrtf(bnv[col + 1] + BN_EPS);
        float m0 = bnm[col], m1 = bnm[col + 1];
        float bb0 = bnb[col], bb1 = bnb[col + 1];
        float f0 = fcb[col], f1 = fcb[col + 1];
        #pragma unroll
        for (int mf = 0; mf < 2; mf++) {
            int r1 = row0 + warpM + mf * 16 + g;
            int r2 = r1 + 8;
            if (r1 < NN) {
                float2 o;
                o.x = fmaxf((c[mf][nf][0] + f0 - m0) * sc0 + bb0, 0.f);
                o.y = fmaxf((c[mf][nf][1] + f1 - m1) * sc1 + bb1, 0.f);
                *(float2*)&out[(long)r1 * HH + col] = o;
            }
            if (r2 < NN) {
                float2 o;
                o.x = fmaxf((c[mf][nf][2] + f0 - m0) * sc0 + bb0, 0.f);
                o.y = fmaxf((c[mf][nf][3] + f1 - m1) * sc1 + bb1, 0.f);
                *(float2*)&out[(long)r2 * HH + col] = o;
            }
        }
    }
}

// ---------------- conv GEMM via HMMA + LDSM (K=64) ----------------
// INHALF=0: A is fp32 [NN][64]; INHALF=1: A is fp16 uint2 [NN][16] (straight copy)
template <int INHALF>
__global__ __launch_bounds__(256)
void gemmh_k(const void* __restrict__ Ain, const __half* __restrict__ Wt,
             uint2* __restrict__ out)
{
    __shared__ __align__(16) __half As[64 * AS_STRIDE];
    __shared__ __align__(16) __half Ws[64 * AS_STRIDE];

    int tid = threadIdx.x;
    int row0 = blockIdx.x * 64;
    int wid = tid >> 5, lane = tid & 31;
    int g = lane >> 2, t = lane & 3;
    int lr = lane & 7, quad = lane >> 3;
    int warpM = (wid & 1) * 32;
    int warpN = (wid >> 1) * 16;

    #pragma unroll
    for (int i = 0; i < 4; i++) {
        int idx = tid + i * 256;
        int r = idx >> 4, c4 = idx & 15;
        int grow = row0 + r;
        uint2 u = make_uint2(0u, 0u);
        if (grow < NN) {
            if (INHALF) {
                u = ((const uint2*)Ain)[grow * 16 + c4];
            } else {
                float4 v = *(const float4*)&((const float*)Ain)[(long)grow * HH + c4 * 4];
                __half2 h01 = __floats2half2_rn(v.x, v.y);
                __half2 h23 = __floats2half2_rn(v.z, v.w);
                u.x = *(unsigned*)&h01;
                u.y = *(unsigned*)&h23;
            }
        }
        *(uint2*)&As[r * AS_STRIDE + c4 * 4] = u;
    }
    {
        const uint4* srcW = (const uint4*)Wt;
        uint4* dstW = (uint4*)Ws;
        #pragma unroll
        for (int i = 0; i < 3; i++) {
            int idx = tid + i * 256;
            if (idx < 64 * AS_STRIDE / 8) dstW[idx] = srcW[idx];
        }
    }
    __syncthreads();

    float c[2][2][4];
    #pragma unroll
    for (int m = 0; m < 2; m++)
        #pragma unroll
        for (int n = 0; n < 2; n++)
            #pragma unroll
            for (int q = 0; q < 4; q++) c[m][n][q] = 0.f;

    int bn = warpN + lr + ((quad & 2) ? 8 : 0);
    int bko = (quad & 1) ? 8 : 0;
    int arl = lr + ((quad & 1) ? 8 : 0);
    int ako = (quad & 2) ? 8 : 0;

    #pragma unroll
    for (int kc = 0; kc < 64; kc += 16) {
        unsigned b0, b1, b2, b3;
        ldsm4(b0, b1, b2, b3, &Ws[bn * AS_STRIDE + kc + bko]);
        #pragma unroll
        for (int mf = 0; mf < 2; mf++) {
            unsigned a0, a1, a2, a3;
            ldsm4(a0, a1, a2, a3, &As[(warpM + mf * 16 + arl) * AS_STRIDE + kc + ako]);
            asm volatile(
                "mma.sync.aligned.m16n8k16.row.col.f32.f16.f16.f32 "
                "{%0,%1,%2,%3}, {%4,%5,%6,%7}, {%8,%9}, {%0,%1,%2,%3};"
                : "+f"(c[mf][0][0]), "+f"(c[mf][0][1]), "+f"(c[mf][0][2]), "+f"(c[mf][0][3])
                : "r"(a0), "r"(a1), "r"(a2), "r"(a3), "r"(b0), "r"(b1));
            asm volatile(
                "mma.sync.aligned.m16n8k16.row.col.f32.f16.f16.f32 "
                "{%0,%1,%2,%3}, {%4,%5,%6,%7}, {%8,%9}, {%0,%1,%2,%3};"
                : "+f"(c[mf][1][0]), "+f"(c[mf][1][1]), "+f"(c[mf][1][2]), "+f"(c[mf][1][3])
                : "r"(a0), "r"(a1), "r"(a2), "r"(a3), "r"(b2), "r"(b3));
        }
    }

    __half* hw = (__half*)out;
    #pragma unroll
    for (int mf = 0; mf < 2; mf++) {
        int r1 = row0 + warpM + mf * 16 + g;
        int r2 = r1 + 8;
        float d1 = (r1 < NN) ? g_dis[r1] : 0.f;
        float d2 = (r2 < NN) ? g_dis[r2] : 0.f;
        #pragma unroll
        for (int nf = 0; nf < 2; nf++) {
            int col = warpN + nf * 8 + 2 * t;
            if (r1 < NN) {
                __half2 h = __floats2half2_rn(c[mf][nf][0] * d1, c[mf][nf][1] * d1);
                *(__half2*)&hw[(long)r1 * HH + col] = h;
            }
            if (r2 < NN) {
                __half2 h = __floats2half2_rn(c[mf][nf][2] * d2, c[mf][nf][3] * d2);
                *(__half2*)&hw[(long)r2 * HH + col] = h;
            }
        }
    }
}

// ---------------- aggregation: 16 threads/node, unroll-4 gathers ----------------
// OUTHALF=0: fp32 float4 out (final). OUTHALF=1: fp16 uint2 out (feeds conv1).
template <int OUTHALF>
__global__ __launch_bounds__(256)
void agg_k(const uint2* __restrict__ hwu,
           const float* __restrict__ cb, const float* __restrict__ bng,
           const float* __restrict__ bnb, const float* __restrict__ bnm,
           const float* __restrict__ bnv, const float* __restrict__ last,
           void* __restrict__ outv)
{
    int gid = blockIdx.x * blockDim.x + threadIdx.x;
    int node = gid >> 4;
    if (node >= NN) return;
    int c4 = gid & 15;

    uint2 rs = hwu[node * 16 + c4];
    float2 f01 = __half22float2(*(const __half2*)&rs.x);
    float2 f23 = __half22float2(*(const __half2*)&rs.y);
    float4 acc = make_float4(f01.x, f01.y, f23.x, f23.y);
    float4 accB = make_float4(0.f, 0.f, 0.f, 0.f);

    int s = g_off[node], e = g_off[node + 1];
    int i = s;
    // unroll-4: 4 gathers in flight; even->acc, odd->accB (same order as unroll-2)
    for (; i + 3 < e; i += 4) {
        int u0 = g_csr[i];
        int u1 = g_csr[i + 1];
        int u2 = g_csr[i + 2];
        int u3 = g_csr[i + 3];
        uint2 r0 = hwu[u0 * 16 + c4];
        uint2 r1 = hwu[u1 * 16 + c4];
        uint2 r2 = hwu[u2 * 16 + c4];
        uint2 r3 = hwu[u3 * 16 + c4];
        float2 a01 = __half22float2(*(const __half2*)&r0.x);
        float2 a23 = __half22float2(*(const __half2*)&r0.y);
        float2 b01 = __half22float2(*(const __half2*)&r1.x);
        float2 b23 = __half22float2(*(const __half2*)&r1.y);
        acc.x += a01.x; acc.y += a01.y; acc.z += a23.x; acc.w += a23.y;
        accB.x += b01.x; accB.y += b01.y; accB.z += b23.x; accB.w += b23.y;
        float2 c01 = __half22float2(*(const __half2*)&r2.x);
        float2 c23 = __half22float2(*(const __half2*)&r2.y);
        float2 d01 = __half22float2(*(const __half2*)&r3.x);
        float2 d23 = __half22float2(*(const __half2*)&r3.y);
        acc.x += c01.x; acc.y += c01.y; acc.z += c23.x; acc.w += c23.y;
        accB.x += d01.x; accB.y += d01.y; accB.z += d23.x; accB.w += d23.y;
    }
    for (; i + 1 < e; i += 2) {
        int u0 = g_csr[i];
        int u1 = g_csr[i + 1];
        uint2 r0 = hwu[u0 * 16 + c4];
        uint2 r1 = hwu[u1 * 16 + c4];
        float2 a01 = __half22float2(*(const __half2*)&r0.x);
        float2 a23 = __half22float2(*(const __half2*)&r0.y);
        float2 b01 = __half22float2(*(const __half2*)&r1.x);
        float2 b23 = __half22float2(*(const __half2*)&r1.y);
        acc.x += a01.x; acc.y += a01.y; acc.z += a23.x; acc.w += a23.y;
        accB.x += b01.x; accB.y += b01.y; accB.z += b23.x; accB.w += b23.y;
    }
    if (i < e) {
        int u = g_csr[i];
        uint2 r0 = hwu[u * 16 + c4];
        float2 a01 = __half22float2(*(const __half2*)&r0.x);
        float2 a23 = __half22float2(*(const __half2*)&r0.y);
        acc.x += a01.x; acc.y += a01.y; acc.z += a23.x; acc.w += a23.y;
    }
    acc.x += accB.x; acc.y += accB.y; acc.z += accB.z; acc.w += accB.w;

    float dn = g_dis[node];
    int c = c4 * 4;
    float4 B  = *(const float4*)&cb[c];
    float4 G  = *(const float4*)&bng[c];
    float4 Be = *(const float4*)&bnb[c];
    float4 M  = *(const float4*)&bnm[c];
    float4 V  = *(const float4*)&bnv[c];
    float4 Ls = ((const float4*)last)[node * 16 + c4];

    float4 o;
    o.x = fmaxf((acc.x * dn + B.x - M.x) * (G.x * rsqrtf(V.x + BN_EPS)) + Be.x, 0.f) + Ls.x;
    o.y = fmaxf((acc.y * dn + B.y - M.y) * (G.y * rsqrtf(V.y + BN_EPS)) + Be.y, 0.f) + Ls.y;
    o.z = fmaxf((acc.z * dn + B.z - M.z) * (G.z * rsqrtf(V.z + BN_EPS)) + Be.z, 0.f) + Ls.z;
    o.w = fmaxf((acc.w * dn + B.w - M.w) * (G.w * rsqrtf(V.w + BN_EPS)) + Be.w, 0.f) + Ls.w;

    if (OUTHALF) {
        __half2 h01 = __floats2half2_rn(o.x, o.y);
        __half2 h23 = __floats2half2_rn(o.z, o.w);
        uint2 u;
        u.x = *(unsigned*)&h01;
        u.y = *(unsigned*)&h23;
        ((uint2*)outv)[node * 16 + c4] = u;
    } else {
        ((float4*)outv)[node * 16 + c4] = o;
    }
}

// ---------------- launch ----------------
// Issue order: wconv(1,s1) zero(2) hist(3) scanfuse(4 -> profiled) fc(5,s1)
//              fill(6) conv0(7,s1) ... join ... agg0(fp16), conv1(fp16 in), agg1
extern "C" void kernel_launch(void* const* d_in, const int* in_sizes, int n_in,
                              void* d_out, int out_size)
{
    const float* x   = (const float*)d_in[0];
    const int*   ei  = (const int*)  d_in[1];
    const float* fcw = (const float*)d_in[2];
    const float* fcb = (const float*)d_in[3];
    const float* cw  = (const float*)d_in[4];
    const float* cb  = (const float*)d_in[5];
    const float* bng = (const float*)d_in[6];
    const float* bnb = (const float*)d_in[7];
    const float* bnm = (const float*)d_in[8];
    const float* bnv = (const float*)d_in[9];
    float* out = (float*)d_out;

    const int* src = ei;
    const int* dst = ei + EE;

    float* ph0;
    uint2 *phw, *ph1h;
    __half *pwt0, *pwt1;
    cudaGetSymbolAddress((void**)&ph0, g_h0);
    cudaGetSymbolAddress((void**)&phw, g_hw16);
    cudaGetSymbolAddress((void**)&ph1h, g_h1h);
    cudaGetSymbolAddress((void**)&pwt0, g_wtcv);
    pwt1 = pwt0 + 64 * AS_STRIDE;

    cudaStream_t s1;
    cudaEvent_t evFork, evScan, evJoin;
    cudaStreamCreateWithFlags(&s1, cudaStreamNonBlocking);
    cudaEventCreateWithFlags(&evFork, cudaEventDisableTiming);
    cudaEventCreateWithFlags(&evScan, cudaEventDisableTiming);
    cudaEventCreateWithFlags(&evJoin, cudaEventDisableTiming);

    const int gblocks = (NN + 63) / 64;
    const int ablocks = (NN * 16 + 255) / 256;

    cudaEventRecord(evFork, 0);
    cudaStreamWaitEvent(s1, evFork, 0);

    // slots 1-4 (slot 4 = new shuffle scan -> profiled)
    wconv_k<<<1, 256, 0, s1>>>(fcw, cw);
    zero_k <<<(NN / 4 + 255) / 256, 256>>>();
    hist_k <<<(EE / 4 + 255) / 256, 256>>>(dst);
    scanfuse_k<<<SCAN_BLOCKS, 1024>>>();
    cudaEventRecord(evScan, 0);               // g_dis + g_cur ready

    // stream s1: fc HMMA
    gemmh_fc_k<<<gblocks, 256, 0, s1>>>(x, ph0, fcb, bng, bnb, bnm, bnv);

    fill_k<<<(EE / 4 + 255) / 256, 256>>>(src, dst);

    // conv0 needs g_dis
    cudaStreamWaitEvent(s1, evScan, 0);
    gemmh_k<0><<<gblocks, 256, 0, s1>>>(ph0, pwt0, phw);

    cudaEventRecord(evJoin, s1);
    cudaStreamWaitEvent(0, evJoin, 0);

    // layer 0 aggregation -> fp16 h1
    agg_k<1><<<ablocks, 256>>>(phw, cb, bng + 64, bnb + 64, bnm + 64, bnv + 64,
                               ph0, ph1h);

    // layer 1: fp16-input HMMA transform, then final aggregation -> d_out
    gemmh_k<1><<<gblocks, 256>>>(ph1h, pwt1, phw);
    agg_k<0><<<ablocks, 256>>>(phw, cb + HH, bng + 128, bnb + 128, bnm + 128, bnv + 128,
                               ph0, out);

    cudaEventDestroy(evFork);
    cudaEventDestroy(evScan);
    cudaEventDestroy(evJoin);
    cudaStreamDestroy(s1);
}